// round 15
// baseline (speedup 1.0000x reference)
#include <cuda_runtime.h>

#define HID   32
#define INDIM 128
#define NMAX  100000
#define EMAX  1600000
#define BMW   ((NMAX + 31) / 32)    // 3125 bitmap words = 12.5 KB

// ---------------- static device scratch (no allocations allowed) ----------------
// All mutable state is reset within the launch sequence (bitmaps/deg in k_agg1,
// counters/a3 in k_tail), so every graph replay sees identical initial state.
__device__ __align__(16) float        g_deg [NMAX];   // reset in k_agg1
__device__ __align__(16) float        g_dinv[NMAX];   // recomputed for F0 nodes
__device__ __align__(16) unsigned int g_bm0[BMW], g_bm1[BMW], g_bm2[BMW]; // reset in k_agg1
__device__ int  g_list0[NMAX], g_list1[NMAX], g_list2[NMAX];
__device__ int2 g_L1[EMAX], g_L2[EMAX], g_L3[EMAX];
__device__ int  g_c0, g_c1, g_c2, g_cL1, g_cL2, g_cL3;                   // reset in k_tail
__device__ __align__(16) float g_y0[(size_t)NMAX * HID];
__device__ __align__(16) float g_y1[(size_t)NMAX * HID];
__device__ __align__(16) float g_y2[(size_t)NMAX * HID];
__device__ __align__(16) float g_a1[(size_t)NMAX * HID];  // rows zeroed on insert
__device__ __align__(16) float g_a2[(size_t)NMAX * HID];  // rows zeroed on insert
__device__ __align__(16) float g_a3[2 * HID];             // reset in k_tail

// ------- frontier insertion: atomicOr dedupe + cascade (ran correctly in R8) ----
__device__ __forceinline__ void add_f0(int n) {
    unsigned int b = 1u << (n & 31);
    if (!(atomicOr(&g_bm0[n >> 5], b) & b))
        g_list0[atomicAdd(&g_c0, 1)] = n;
}
__device__ __forceinline__ void add_f1(int n) {
    unsigned int b = 1u << (n & 31);
    if (!(atomicOr(&g_bm1[n >> 5], b) & b)) {
        g_list1[atomicAdd(&g_c1, 1)] = n;
        float4* a = (float4*)(g_a1 + (size_t)n * HID);
        float4 z = make_float4(0.f, 0.f, 0.f, 0.f);
        #pragma unroll
        for (int j = 0; j < 8; j++) a[j] = z;
        add_f0(n);
    }
}
__device__ __forceinline__ void add_f2(int n) {
    unsigned int b = 1u << (n & 31);
    if (!(atomicOr(&g_bm2[n >> 5], b) & b)) {
        g_list2[atomicAdd(&g_c2, 1)] = n;
        float4* a = (float4*)(g_a2 + (size_t)n * HID);
        float4 z = make_float4(0.f, 0.f, 0.f, 0.f);
        #pragma unroll
        for (int j = 0; j < 8; j++) a[j] = z;
        add_f1(n);
    }
}

// ---------------- edge scan kernel, templated on phase (loader from R11) --------
// MODE 0: dst<2    -> L3 + cascade F2
// MODE 1: bm2[dst] -> L2 + cascade F1 (+F0)
// MODE 2: bm1[dst] -> L1 + cascade F0; deg[dst]++ for EVERY edge (folded, R14)
template<int MODE>
__global__ void __launch_bounds__(1024) k_scan(const void* __restrict__ ei, int E) {
    __shared__ unsigned int s_bm[BMW];
    __shared__ int s_i64;

    const int tid  = threadIdx.x;
    const int lane = tid & 31;
    if (tid == 0) s_i64 = 1;
    __syncthreads();
    {   // parallel int64/int32 detection: int64 => high word of every element is 0
        const unsigned int* w = (const unsigned int*)ei;
        int lim = (2 * E < 2048) ? 2 * E : 2048;
        for (int k = 2 * tid + 1; k < lim; k += 2048)
            if (w[k]) s_i64 = 0;                   // benign same-value race
    }
    if (MODE >= 1) {
        const unsigned int* bm = (MODE == 1) ? g_bm2 : g_bm1;
        for (int i = tid; i < BMW; i += 1024) s_bm[i] = bm[i];
    }
    __syncthreads();
    const int i64 = s_i64;

    int2* Lg = (MODE == 0) ? g_L3 : (MODE == 1) ? g_L2 : g_L1;
    int*  cg = (MODE == 0) ? &g_cL3 : (MODE == 1) ? &g_cL2 : &g_cL1;

    if (MODE == 0 && blockIdx.x == 0 && tid == 0) { add_f2(0); add_f2(1); }

    auto process = [&](int e, int d) {
        if (MODE == 2) atomicAdd(&g_deg[d], 1.0f);       // spread REDG, overlapped
        bool hit = (MODE == 0) ? (d < 2) : (((s_bm[d >> 5] >> (d & 31)) & 1u) != 0);
        if (!hit) return;
        int s = i64 ? (int)((const long long*)ei)[e] : ((const int*)ei)[e];
        Lg[atomicAdd(cg, 1)] = make_int2(s, d);
        if (MODE == 0) add_f2(s);
        else if (MODE == 1) add_f1(s);
        else add_f0(s);
    };

    const int gwarp  = (blockIdx.x * 1024 + tid) >> 5;
    const int nwarps = (gridDim.x * 1024) >> 5;
    const int gt     = blockIdx.x * 1024 + tid;
    const int gs     = gridDim.x * 1024;

    if (i64) {
        const long long* dst = (const long long*)ei + E;
        if ((((size_t)dst) & 15) == 0) {
            const longlong2* dst2 = (const longlong2*)dst;
            const int V = E >> 1;
            for (int v0 = gwarp * 256; v0 < V; v0 += nwarps * 256) {
                longlong2 dd[8];
                int vv[8];
                #pragma unroll
                for (int j = 0; j < 8; j++) {
                    vv[j] = v0 + j * 32 + lane;                // coalesced, MLP=8
                    if (vv[j] < V) dd[j] = dst2[vv[j]];
                }
                #pragma unroll
                for (int j = 0; j < 8; j++) {
                    if (vv[j] < V) {
                        process(2 * vv[j],     (int)dd[j].x);
                        process(2 * vv[j] + 1, (int)dd[j].y);
                    }
                }
            }
            for (int e = 2 * V + gt; e < E; e += gs) process(e, (int)dst[e]);
        } else {
            for (int e = gt; e < E; e += gs) process(e, (int)dst[e]);
        }
    } else {
        const int* dst = (const int*)ei + E;
        if ((((size_t)dst) & 15) == 0) {
            const int4* dst4 = (const int4*)dst;
            const int V = E >> 2;
            for (int v0 = gwarp * 256; v0 < V; v0 += nwarps * 256) {
                int4 dd[8];
                int vv[8];
                #pragma unroll
                for (int j = 0; j < 8; j++) {
                    vv[j] = v0 + j * 32 + lane;
                    if (vv[j] < V) dd[j] = dst4[vv[j]];
                }
                #pragma unroll
                for (int j = 0; j < 8; j++) {
                    if (vv[j] < V) {
                        process(4 * vv[j],     dd[j].x);
                        process(4 * vv[j] + 1, dd[j].y);
                        process(4 * vv[j] + 2, dd[j].z);
                        process(4 * vv[j] + 3, dd[j].w);
                    }
                }
            }
            for (int e = 4 * V + gt; e < E; e += gs) process(e, dst[e]);
        } else {
            for (int e = gt; e < E; e += gs) process(e, dst[e]);
        }
    }
}

// ---------------- y0 = x @ W1 + dinv for F0 nodes (warp per node, R4-proven) ----
__global__ void __launch_bounds__(256) k_y0(const float* __restrict__ x,
                                            const float* __restrict__ W1) {
    int wid  = (blockIdx.x * 256 + threadIdx.x) >> 5;
    int lane = threadIdx.x & 31;
    int nw   = (gridDim.x * 256) >> 5;
    int cnt  = g_c0;
    for (int i = wid; i < cnt; i += nw) {
        int n = g_list0[i];                                  // broadcast load
        if (lane == 0) g_dinv[n] = rsqrtf(g_deg[n] + 1.0f);  // +1 self-loop
        const float* xr = x + (size_t)n * INDIM;
        float xv0 = xr[lane], xv1 = xr[lane + 32], xv2 = xr[lane + 64], xv3 = xr[lane + 96];
        float acc = 0.f;
        #pragma unroll
        for (int k = 0; k < 32; k++)
            acc = fmaf(__shfl_sync(0xffffffffu, xv0, k), W1[(k      ) * HID + lane], acc);
        #pragma unroll
        for (int k = 0; k < 32; k++)
            acc = fmaf(__shfl_sync(0xffffffffu, xv1, k), W1[(k +  32) * HID + lane], acc);
        #pragma unroll
        for (int k = 0; k < 32; k++)
            acc = fmaf(__shfl_sync(0xffffffffu, xv2, k), W1[(k +  64) * HID + lane], acc);
        #pragma unroll
        for (int k = 0; k < 32; k++)
            acc = fmaf(__shfl_sync(0xffffffffu, xv3, k), W1[(k +  96) * HID + lane], acc);
        g_y0[(size_t)n * HID + lane] = acc;
    }
}

// ---------------- edge aggregation: A[dst] += dinv[s]*dinv[d]*Y[src] ------------
__device__ __forceinline__ void agg_edges(const int2* __restrict__ L, int cnt,
                                          const float* __restrict__ Y, float* __restrict__ A,
                                          int warp, int nwarps, int lane) {
    for (int i = warp; i < cnt; i += nwarps) {
        int2 ed = L[i];                              // all lanes same addr: broadcast
        float w = g_dinv[ed.x] * g_dinv[ed.y];
        atomicAdd(&A[(size_t)ed.y * HID + lane], w * Y[(size_t)ed.x * HID + lane]);
    }
}

// ------- agg1 over L1 + grid-wide reset of deg + bitmaps (dead after k_y0) ------
__global__ void __launch_bounds__(256) k_agg1(int N) {
    int gt = blockIdx.x * 256 + threadIdx.x;
    int gs = gridDim.x * 256;
    for (int i = gt; i < N; i += gs) g_deg[i] = 0.f;
    for (int w = gt; w < BMW; w += gs) { g_bm0[w] = 0u; g_bm1[w] = 0u; g_bm2[w] = 0u; }
    agg_edges(g_L1, g_cL1, g_y0, g_a1, gt >> 5, gs >> 5, threadIdx.x & 31);
}

// ------- node update: h = relu(A + dinv^2*Yin + b); Yout = h @ W (32x32) --------
__device__ __forceinline__ void layer_nodes(const int* __restrict__ list, int cnt,
                                            const float* __restrict__ A,
                                            const float* __restrict__ Yin,
                                            const float* __restrict__ b,
                                            const float* __restrict__ W,
                                            float* __restrict__ Yout,
                                            int warp, int nwarps, int lane) {
    for (int i = warp; i < cnt; i += nwarps) {
        int n = list[i];
        float dv = g_dinv[n];
        float h = A[(size_t)n * HID + lane] + dv * dv * Yin[(size_t)n * HID + lane] + b[lane];
        h = fmaxf(h, 0.f);
        float acc = 0.f;
        #pragma unroll
        for (int k = 0; k < HID; k++)
            acc = fmaf(__shfl_sync(0xffffffffu, h, k), W[k * HID + lane], acc);
        Yout[(size_t)n * HID + lane] = acc;
    }
}

// -- tail: layer1 + agg2 + layer2 + agg3 + final + counter reset (single block) --
__global__ void __launch_bounds__(1024) k_tail(const float* __restrict__ b1,
                                               const float* __restrict__ W2,
                                               const float* __restrict__ b2,
                                               const float* __restrict__ W3,
                                               const float* __restrict__ b3,
                                               const float* __restrict__ Wfc,
                                               const float* __restrict__ bfc,
                                               float* __restrict__ out) {
    __shared__ float s_z[2 * HID];
    const int tid  = threadIdx.x;
    const int warp = tid >> 5;                     // 0..31
    const int lane = tid & 31;

    // layer-1 node update -> y1 (|F1| ~ hundreds)
    layer_nodes(g_list1, g_c1, g_a1, g_y0, b1, W2, g_y1, warp, 32, lane);
    __threadfence(); __syncthreads();

    // agg2 over L2 (~hundreds of edges)
    agg_edges(g_L2, g_cL2, g_y1, g_a2, warp, 32, lane);
    __threadfence(); __syncthreads();

    // layer-2 node update -> y2 (|F2| ~ tens)
    layer_nodes(g_list2, g_c2, g_a2, g_y1, b2, W3, g_y2, warp, 32, lane);
    __threadfence(); __syncthreads();

    // agg3 over L3 (edges into nodes 0,1)
    agg_edges(g_L3, g_cL3, g_y2, g_a3, warp, 32, lane);
    __threadfence(); __syncthreads();

    // final: h3 at {0,1}; z = concat(h3[0], h3[1]); out = z @ Wfc + bfc
    if (tid < 2 * HID) {
        int node = tid >> 5;
        float dv = g_dinv[node];
        float h = g_a3[tid] + dv * dv * g_y2[(size_t)node * HID + lane] + b3[lane];
        s_z[tid] = fmaxf(h, 0.f);
    }
    __syncthreads();
    if (tid < 64) {
        float acc = bfc[tid];
        #pragma unroll
        for (int i = 0; i < 2 * HID; i++)
            acc = fmaf(s_z[i], Wfc[i * 64 + tid], acc);
        out[tid] = acc;
    }
    __syncthreads();

    // ---- reset remaining state for the next graph replay ----
    if (tid < 2 * HID) g_a3[tid] = 0.f;
    __syncthreads();
    if (tid == 0) { g_c0 = 0; g_c1 = 0; g_c2 = 0; g_cL1 = 0; g_cL2 = 0; g_cL3 = 0; }
}

// ---------------- launcher: 6 kernels -------------------------------------------
extern "C" void kernel_launch(void* const* d_in, const int* in_sizes, int n_in,
                              void* d_out, int out_size) {
    const float* x   = (const float*)d_in[0];
    const void*  ei  = d_in[1];               // int64 or int32, auto-detected
    const float* W1  = (const float*)d_in[2];
    const float* b1  = (const float*)d_in[3];
    const float* W2  = (const float*)d_in[4];
    const float* b2  = (const float*)d_in[5];
    const float* W3  = (const float*)d_in[6];
    const float* b3  = (const float*)d_in[7];
    const float* Wfc = (const float*)d_in[8];
    const float* bfc = (const float*)d_in[9];
    float* out = (float*)d_out;

    int N = in_sizes[0] / INDIM;
    int E = in_sizes[1] / 2;

    int dev = 0, sm = 0;
    cudaGetDevice(&dev);
    cudaDeviceGetAttribute(&sm, cudaDevAttrMultiProcessorCount, dev);
    if (sm <= 0) sm = 148;
    int sb = ((E >> 1) + 8191) / 8192;        // one 256-vector batch per warp
    if (sb > sm) sb = sm;                     // grid-stride covers the rest
    if (sb < 1) sb = 1;

    k_scan<0><<<sb, 1024>>>(ei, E);           // L3 + F2 (cascade fills all lists)
    k_scan<1><<<sb, 1024>>>(ei, E);           // L2 + F1
    k_scan<2><<<sb, 1024>>>(ei, E);           // L1 + F0 + degrees (folded)
    k_y0   <<<256, 256>>>(x, W1);             // dinv + x@W1 on F0
    k_agg1 <<<148, 256>>>(N);                 // layer-1 aggregation + state reset
    k_tail <<<1, 1024>>>(b1, W2, b2, W3, b3, Wfc, bfc, out);
}

// round 16
// speedup vs baseline: 1.2774x; 1.2774x over previous
#include <cuda_runtime.h>

#define HID   32
#define INDIM 128
#define NMAX  100000
#define EMAX  1600000
#define BMW   ((NMAX + 31) / 32)    // 3125 bitmap words = 12.5 KB

// ---------------- static device scratch (no allocations allowed) ----------------
// All mutable state is reset within the launch sequence (bitmaps in k_agg1x,
// deg/counters/a3 in k_tail), so every graph replay sees identical initial state.
__device__ __align__(16) float        g_deg [NMAX];   // reset in k_tail (after last use)
__device__ __align__(16) unsigned int g_bm1[BMW], g_bm2[BMW];  // reset in k_agg1x
__device__ int  g_list1[NMAX], g_list2[NMAX];
__device__ int2 g_L1[EMAX], g_L2[EMAX], g_L3[EMAX];
__device__ int  g_c1, g_c2, g_cL1, g_cL2, g_cL3;               // reset in k_tail
__device__ __align__(16) float g_ax1[(size_t)NMAX * INDIM];    // x-space accum; rows zeroed on insert
__device__ __align__(16) float g_y1[(size_t)NMAX * HID];
__device__ __align__(16) float g_y2[(size_t)NMAX * HID];
__device__ __align__(16) float g_a2[(size_t)NMAX * HID];       // rows zeroed on insert
__device__ __align__(16) float g_a3[2 * HID];                  // reset in k_tail

// ------- frontier insertion: atomicOr dedupe (pattern proven R14/R15) -----------
__device__ __forceinline__ void add_f1(int n) {
    unsigned int b = 1u << (n & 31);
    if (!(atomicOr(&g_bm1[n >> 5], b) & b)) {
        g_list1[atomicAdd(&g_c1, 1)] = n;
        float4* a = (float4*)(g_ax1 + (size_t)n * INDIM);      // zero 128-float row
        float4 z = make_float4(0.f, 0.f, 0.f, 0.f);
        #pragma unroll
        for (int j = 0; j < 32; j++) a[j] = z;
    }
}
__device__ __forceinline__ void add_f2(int n) {
    unsigned int b = 1u << (n & 31);
    if (!(atomicOr(&g_bm2[n >> 5], b) & b)) {
        g_list2[atomicAdd(&g_c2, 1)] = n;
        float4* a = (float4*)(g_a2 + (size_t)n * HID);         // zero 32-float row
        float4 z = make_float4(0.f, 0.f, 0.f, 0.f);
        #pragma unroll
        for (int j = 0; j < 8; j++) a[j] = z;
        add_f1(n);
    }
}

// ---------------- edge scan kernel, templated on phase (loader proven R14/R15) --
// MODE 0: dst<2    -> L3 + cascade F2 (which zeroes a2 + cascades F1/ax1)
// MODE 1: bm2[dst] -> L2 + cascade F1
// MODE 2: bm1[dst] -> L1 append only;  deg[dst]++ for EVERY edge (folded)
template<int MODE>
__global__ void __launch_bounds__(1024) k_scan(const void* __restrict__ ei, int E) {
    __shared__ unsigned int s_bm[BMW];
    __shared__ int s_i64;

    const int tid  = threadIdx.x;
    const int lane = tid & 31;
    if (tid == 0) s_i64 = 1;
    __syncthreads();
    {   // parallel int64/int32 detection: int64 => high word of every element is 0
        const unsigned int* w = (const unsigned int*)ei;
        int lim = (2 * E < 2048) ? 2 * E : 2048;
        for (int k = 2 * tid + 1; k < lim; k += 2048)
            if (w[k]) s_i64 = 0;                   // benign same-value race
    }
    if (MODE >= 1) {
        const unsigned int* bm = (MODE == 1) ? g_bm2 : g_bm1;
        for (int i = tid; i < BMW; i += 1024) s_bm[i] = bm[i];
    }
    __syncthreads();
    const int i64 = s_i64;

    int2* Lg = (MODE == 0) ? g_L3 : (MODE == 1) ? g_L2 : g_L1;
    int*  cg = (MODE == 0) ? &g_cL3 : (MODE == 1) ? &g_cL2 : &g_cL1;

    if (MODE == 0 && blockIdx.x == 0 && tid == 0) { add_f2(0); add_f2(1); }

    auto process = [&](int e, int d) {
        if (MODE == 2) atomicAdd(&g_deg[d], 1.0f);       // spread REDG, overlapped
        bool hit = (MODE == 0) ? (d < 2) : (((s_bm[d >> 5] >> (d & 31)) & 1u) != 0);
        if (!hit) return;
        int s = i64 ? (int)((const long long*)ei)[e] : ((const int*)ei)[e];
        Lg[atomicAdd(cg, 1)] = make_int2(s, d);
        if (MODE == 0) add_f2(s);
        else if (MODE == 1) add_f1(s);
        // MODE 2: append only — no F0 frontier needed
    };

    const int gwarp  = (blockIdx.x * 1024 + tid) >> 5;
    const int nwarps = (gridDim.x * 1024) >> 5;
    const int gt     = blockIdx.x * 1024 + tid;
    const int gs     = gridDim.x * 1024;

    if (i64) {
        const long long* dst = (const long long*)ei + E;
        if ((((size_t)dst) & 15) == 0) {
            const longlong2* dst2 = (const longlong2*)dst;
            const int V = E >> 1;
            for (int v0 = gwarp * 256; v0 < V; v0 += nwarps * 256) {
                longlong2 dd[8];
                int vv[8];
                #pragma unroll
                for (int j = 0; j < 8; j++) {
                    vv[j] = v0 + j * 32 + lane;                // coalesced, MLP=8
                    if (vv[j] < V) dd[j] = dst2[vv[j]];
                }
                #pragma unroll
                for (int j = 0; j < 8; j++) {
                    if (vv[j] < V) {
                        process(2 * vv[j],     (int)dd[j].x);
                        process(2 * vv[j] + 1, (int)dd[j].y);
                    }
                }
            }
            for (int e = 2 * V + gt; e < E; e += gs) process(e, (int)dst[e]);
        } else {
            for (int e = gt; e < E; e += gs) process(e, (int)dst[e]);
        }
    } else {
        const int* dst = (const int*)ei + E;
        if ((((size_t)dst) & 15) == 0) {
            const int4* dst4 = (const int4*)dst;
            const int V = E >> 2;
            for (int v0 = gwarp * 256; v0 < V; v0 += nwarps * 256) {
                int4 dd[8];
                int vv[8];
                #pragma unroll
                for (int j = 0; j < 8; j++) {
                    vv[j] = v0 + j * 32 + lane;
                    if (vv[j] < V) dd[j] = dst4[vv[j]];
                }
                #pragma unroll
                for (int j = 0; j < 8; j++) {
                    if (vv[j] < V) {
                        process(4 * vv[j],     dd[j].x);
                        process(4 * vv[j] + 1, dd[j].y);
                        process(4 * vv[j] + 2, dd[j].z);
                        process(4 * vv[j] + 3, dd[j].w);
                    }
                }
            }
            for (int e = 4 * V + gt; e < E; e += gs) process(e, dst[e]);
        } else {
            for (int e = gt; e < E; e += gs) process(e, dst[e]);
        }
    }
}

// ------ agg1x: ax1[dst] += w(s,d) * x[src]  (x-space; warp per edge) ------------
// Also resets the bitmaps (dead after scan<2>'s smem copy).
__global__ void __launch_bounds__(256) k_agg1x(const float* __restrict__ x) {
    int gt   = blockIdx.x * 256 + threadIdx.x;
    int gs   = gridDim.x * 256;
    int warp = gt >> 5;
    int lane = threadIdx.x & 31;
    int nw   = gs >> 5;
    for (int w = gt; w < BMW; w += gs) { g_bm1[w] = 0u; g_bm2[w] = 0u; }
    int cnt = g_cL1;
    for (int i = warp; i < cnt; i += nw) {
        int2 ed = g_L1[i];                                   // broadcast
        float w = rsqrtf(g_deg[ed.x] + 1.0f) * rsqrtf(g_deg[ed.y] + 1.0f);
        const float* xs = x + (size_t)ed.x * INDIM;
        float* ad = g_ax1 + (size_t)ed.y * INDIM;
        #pragma unroll
        for (int j = 0; j < 4; j++)
            atomicAdd(&ad[lane + 32 * j], w * xs[lane + 32 * j]);
    }
}

// ------ layer1: h1 = relu((ax1 + dinv^2*x) @ W1 + b1);  y1 = h1 @ W2 ------------
__global__ void __launch_bounds__(256) k_layer1(const float* __restrict__ x,
                                                const float* __restrict__ W1,
                                                const float* __restrict__ b1,
                                                const float* __restrict__ W2) {
    int warp = (blockIdx.x * 256 + threadIdx.x) >> 5;
    int lane = threadIdx.x & 31;
    int nw   = (gridDim.x * 256) >> 5;
    int cnt  = g_c1;
    for (int i = warp; i < cnt; i += nw) {
        int n = g_list1[i];                                  // broadcast
        float dv = rsqrtf(g_deg[n] + 1.0f);
        float c  = dv * dv;
        const float* xs = x     + (size_t)n * INDIM;
        const float* ax = g_ax1 + (size_t)n * INDIM;
        float v0 = ax[lane]      + c * xs[lane];
        float v1 = ax[lane + 32] + c * xs[lane + 32];
        float v2 = ax[lane + 64] + c * xs[lane + 64];
        float v3 = ax[lane + 96] + c * xs[lane + 96];
        float h0 = 0.f, h1 = 0.f;
        #pragma unroll
        for (int k = 0; k < 32; k++) {
            h0 = fmaf(__shfl_sync(0xffffffffu, v0, k), W1[(k      ) * HID + lane], h0);
            h1 = fmaf(__shfl_sync(0xffffffffu, v1, k), W1[(k +  32) * HID + lane], h1);
        }
        #pragma unroll
        for (int k = 0; k < 32; k++) {
            h0 = fmaf(__shfl_sync(0xffffffffu, v2, k), W1[(k +  64) * HID + lane], h0);
            h1 = fmaf(__shfl_sync(0xffffffffu, v3, k), W1[(k +  96) * HID + lane], h1);
        }
        float h = fmaxf(h0 + h1 + b1[lane], 0.f);
        float acc = 0.f;
        #pragma unroll
        for (int k = 0; k < HID; k++)
            acc = fmaf(__shfl_sync(0xffffffffu, h, k), W2[k * HID + lane], acc);
        g_y1[(size_t)n * HID + lane] = acc;
    }
}

// ---------------- edge aggregation in hidden space (w from deg) -----------------
__device__ __forceinline__ void agg_edges(const int2* __restrict__ L, int cnt,
                                          const float* __restrict__ Y, float* __restrict__ A,
                                          int warp, int nwarps, int lane) {
    for (int i = warp; i < cnt; i += nwarps) {
        int2 ed = L[i];                                      // broadcast
        float w = rsqrtf(g_deg[ed.x] + 1.0f) * rsqrtf(g_deg[ed.y] + 1.0f);
        atomicAdd(&A[(size_t)ed.y * HID + lane], w * Y[(size_t)ed.x * HID + lane]);
    }
}

// ------- node update: h = relu(A + dinv^2*Yin + b); Yout = h @ W (32x32) --------
__device__ __forceinline__ void layer_nodes(const int* __restrict__ list, int cnt,
                                            const float* __restrict__ A,
                                            const float* __restrict__ Yin,
                                            const float* __restrict__ b,
                                            const float* __restrict__ W,
                                            float* __restrict__ Yout,
                                            int warp, int nwarps, int lane) {
    for (int i = warp; i < cnt; i += nwarps) {
        int n = list[i];
        float dv = rsqrtf(g_deg[n] + 1.0f);
        float h = A[(size_t)n * HID + lane] + dv * dv * Yin[(size_t)n * HID + lane] + b[lane];
        h = fmaxf(h, 0.f);
        float acc = 0.f;
        #pragma unroll
        for (int k = 0; k < HID; k++)
            acc = fmaf(__shfl_sync(0xffffffffu, h, k), W[k * HID + lane], acc);
        Yout[(size_t)n * HID + lane] = acc;
    }
}

// -- tail: agg2 + layer2 + agg3 + final + deg/counter reset (single block) -------
__global__ void __launch_bounds__(1024) k_tail(const float* __restrict__ b2,
                                               const float* __restrict__ W3,
                                               const float* __restrict__ b3,
                                               const float* __restrict__ Wfc,
                                               const float* __restrict__ bfc,
                                               float* __restrict__ out, int N) {
    __shared__ float s_z[2 * HID];
    const int tid  = threadIdx.x;
    const int warp = tid >> 5;                     // 0..31
    const int lane = tid & 31;

    // agg2 over L2 (~hundreds of edges): a2[dst] += w * y1[src]
    agg_edges(g_L2, g_cL2, g_y1, g_a2, warp, 32, lane);
    __threadfence(); __syncthreads();

    // layer-2 node update -> y2 (|F2| ~ tens)
    layer_nodes(g_list2, g_c2, g_a2, g_y1, b2, W3, g_y2, warp, 32, lane);
    __threadfence(); __syncthreads();

    // agg3 over L3 (edges into nodes 0,1)
    agg_edges(g_L3, g_cL3, g_y2, g_a3, warp, 32, lane);
    __threadfence(); __syncthreads();

    // final: h3 at {0,1}; z = concat(h3[0], h3[1]); out = z @ Wfc + bfc
    if (tid < 2 * HID) {
        int node = tid >> 5;
        float dv = rsqrtf(g_deg[node] + 1.0f);
        float h = g_a3[tid] + dv * dv * g_y2[(size_t)node * HID + lane] + b3[lane];
        s_z[tid] = fmaxf(h, 0.f);
    }
    __syncthreads();
    if (tid < 64) {
        float acc = bfc[tid];
        #pragma unroll
        for (int i = 0; i < 2 * HID; i++)
            acc = fmaf(s_z[i], Wfc[i * 64 + tid], acc);
        out[tid] = acc;
    }
    __syncthreads();

    // ---- reset remaining state for the next graph replay (deg last use above) --
    float4* dz = (float4*)g_deg;
    int nv = N >> 2;
    for (int i = tid; i < nv; i += 1024) dz[i] = make_float4(0.f, 0.f, 0.f, 0.f);
    for (int i = 4 * nv + tid; i < N; i += 1024) g_deg[i] = 0.f;
    if (tid < 2 * HID) g_a3[tid] = 0.f;
    __syncthreads();
    if (tid == 0) { g_c1 = 0; g_c2 = 0; g_cL1 = 0; g_cL2 = 0; g_cL3 = 0; }
}

// ---------------- launcher: 6 kernels -------------------------------------------
extern "C" void kernel_launch(void* const* d_in, const int* in_sizes, int n_in,
                              void* d_out, int out_size) {
    const float* x   = (const float*)d_in[0];
    const void*  ei  = d_in[1];               // int64 or int32, auto-detected
    const float* W1  = (const float*)d_in[2];
    const float* b1  = (const float*)d_in[3];
    const float* W2  = (const float*)d_in[4];
    const float* b2  = (const float*)d_in[5];
    const float* W3  = (const float*)d_in[6];
    const float* b3  = (const float*)d_in[7];
    const float* Wfc = (const float*)d_in[8];
    const float* bfc = (const float*)d_in[9];
    float* out = (float*)d_out;

    int N = in_sizes[0] / INDIM;
    int E = in_sizes[1] / 2;

    int dev = 0, sm = 0;
    cudaGetDevice(&dev);
    cudaDeviceGetAttribute(&sm, cudaDevAttrMultiProcessorCount, dev);
    if (sm <= 0) sm = 148;
    int sb = ((E >> 1) + 8191) / 8192;        // one 256-vector batch per warp
    if (sb > sm) sb = sm;                     // grid-stride covers the rest
    if (sb < 1) sb = 1;

    k_scan<0><<<sb, 1024>>>(ei, E);           // L3 + F2 (cascades F1, zeroes rows)
    k_scan<1><<<sb, 1024>>>(ei, E);           // L2 + F1
    k_scan<2><<<sb, 1024>>>(ei, E);           // L1 append + degrees (folded)
    k_agg1x <<<128, 256>>>(x);                // x-space aggregation + bitmap reset
    k_layer1<<<32, 256>>>(x, W1, b1, W2);     // F1 GEMVs -> y1
    k_tail  <<<1, 1024>>>(b2, W3, b3, Wfc, bfc, out, N);
}